// round 9
// baseline (speedup 1.0000x reference)
#include <cuda_runtime.h>
#include <cuda_bf16.h>
#include <cuda_fp16.h>
#include <cstdint>

#define NN    100000
#define EE    1600000
#define INC   256
#define OUTC  128

// ------------------------- device scratch -------------------------
__device__ __half        g_Hh[(size_t)NN * OUTC];    // H = X @ W^T (fp16)
__device__ int           g_row_ptr[NN + 1];
__device__ __nv_bfloat16 g_Whi[OUTC * INC];
__device__ __nv_bfloat16 g_Wlo[OUTC * INC];

// ------------------------- helpers -------------------------
__device__ __forceinline__ uint32_t smem_u32(const void* p) {
    uint32_t a;
    asm("{ .reg .u64 t; cvta.to.shared.u64 t, %1; cvt.u32.u64 %0, t; }"
        : "=r"(a) : "l"(p));
    return a;
}
__device__ __forceinline__ void cp_async16(uint32_t dst, const void* src) {
    asm volatile("cp.async.cg.shared.global [%0], [%1], 16;"
                 :: "r"(dst), "l"(src) : "memory");
}
__device__ __forceinline__ void cp_commit() {
    asm volatile("cp.async.commit_group;" ::: "memory");
}
__device__ __forceinline__ void cp_wait0() {
    asm volatile("cp.async.wait_group 0;" ::: "memory");
}

__device__ __forceinline__ void ldm_x4(uint32_t* r, uint32_t addr) {
    asm volatile("ldmatrix.sync.aligned.m8n8.x4.shared.b16 {%0,%1,%2,%3}, [%4];"
                 : "=r"(r[0]), "=r"(r[1]), "=r"(r[2]), "=r"(r[3]) : "r"(addr));
}
__device__ __forceinline__ void ldm_x2(uint32_t* r, uint32_t addr) {
    asm volatile("ldmatrix.sync.aligned.m8n8.x2.shared.b16 {%0,%1}, [%2];"
                 : "=r"(r[0]), "=r"(r[1]) : "r"(addr));
}
__device__ __forceinline__ void mma_bf16(float* c, const uint32_t* a, const uint32_t* b) {
    asm volatile(
        "mma.sync.aligned.m16n8k16.row.col.f32.bf16.bf16.f32 "
        "{%0,%1,%2,%3}, {%4,%5,%6,%7}, {%8,%9}, {%0,%1,%2,%3};"
        : "+f"(c[0]), "+f"(c[1]), "+f"(c[2]), "+f"(c[3])
        : "r"(a[0]), "r"(a[1]), "r"(a[2]), "r"(a[3]), "r"(b[0]), "r"(b[1]));
}

// ------------------------- Kernel 0: split W into bf16 hi/lo -------------------------
__global__ void wconv_kernel(const float* __restrict__ W) {
    int i = blockIdx.x * blockDim.x + threadIdx.x;
    if (i < OUTC * INC) {
        float w = W[i];
        __nv_bfloat16 h = __float2bfloat16(w);
        float r = w - __bfloat162float(h);
        g_Whi[i] = h;
        g_Wlo[i] = __float2bfloat16(r);
    }
}

// ------------------------- Kernel 1: mma.sync bf16 split GEMM (pipelined) -----------
// CTA tile 128x128, K-tiles of 64. 8 warps: warp_m = wid%4, warp_n = wid/4.
// 3 products per fragment: hi*hi + hi*lo + lo*hi.
// Pipeline: X tile t+1 prefetched into registers during compute of tile t;
// W tiles double-buffered in SMEM via cp.async.
//
// SMEM halves layout (LDH=72 pad, conflict-free ldmatrix):
//   A_hi[128][72], A_lo[128][72]  (single buffer)
//   W stages s=0,1: Whi_s[128][72], Wlo_s[128][72]
#define LDH 72
#define SM_AHI 0
#define SM_ALO 9216
#define SM_W   18432
#define SM_WSTRIDE 18432
#define SM_TOTAL_HALVES 55296
#define SM_BYTES (SM_TOTAL_HALVES * 2)   // 110592

__global__ __launch_bounds__(256, 2)
void gemm_tc_kernel(const float* __restrict__ X)
{
    extern __shared__ __half sm[];
    const uint32_t sb = smem_u32(sm);

    const int tid = threadIdx.x;
    const int wid = tid >> 5;
    const int lane = tid & 31;
    const int block_row = blockIdx.x * 128;

    const int wm = (wid & 3) * 32;
    const int wn = (wid >> 2) * 64;

    float c[2][8][4];
#pragma unroll
    for (int mi = 0; mi < 2; mi++)
#pragma unroll
        for (int ni = 0; ni < 8; ni++)
#pragma unroll
            for (int j = 0; j < 4; j++)
                c[mi][ni][j] = 0.0f;

    const int a_row = (lane & 7) + 8 * ((lane >> 3) & 1);
    const int a_kh  = 8 * (lane >> 4);
    const int l2    = lane & 15;
    const int b_row = l2 & 7;
    const int b_kh  = 8 * (l2 >> 3);

    // per-thread X slot mapping (8 float4 per tile)
    float4 xreg[8];
    // prologue: X tile 0 -> regs, W tile 0 -> smem stage 0 (cp.async)
#pragma unroll
    for (int i = 0; i < 8; i++) {
        int slot = i * 256 + tid;
        int row  = slot >> 4;
        int kq   = (slot & 15) << 2;
        int gm   = block_row + row;
        xreg[i] = make_float4(0.f, 0.f, 0.f, 0.f);
        if (gm < NN)
            xreg[i] = *reinterpret_cast<const float4*>(X + (size_t)gm * INC + kq);
    }
#pragma unroll
    for (int i = 0; i < 4; i++) {
        int slot = i * 256 + tid;          // 0..1023
        int n    = slot >> 3;
        int kc   = (slot & 7) << 3;
        int off  = n * LDH + kc;
        cp_async16(sb + 2 * (SM_W + off), g_Whi + n * INC + kc);
        cp_async16(sb + 2 * (SM_W + SM_WSTRIDE / 2 * 0 + 9216 + off), g_Wlo + n * INC + kc);
    }
    cp_commit();

#pragma unroll 1
    for (int kt = 0; kt < 4; kt++) {
        const int buf = kt & 1;
        const int whi = SM_W + buf * SM_WSTRIDE;
        const int wlo = whi + 9216;

        // (a) convert prefetched X regs -> A smem (hi/lo, bf16)
#pragma unroll
        for (int i = 0; i < 8; i++) {
            int slot = i * 256 + tid;
            int row  = slot >> 4;
            int kq   = (slot & 15) << 2;
            float4 v = xreg[i];
            __nv_bfloat16 h0 = __float2bfloat16(v.x);
            __nv_bfloat16 h1 = __float2bfloat16(v.y);
            __nv_bfloat16 h2 = __float2bfloat16(v.z);
            __nv_bfloat16 h3 = __float2bfloat16(v.w);
            __nv_bfloat162 hp0(h0, h1), hp1(h2, h3);
            __nv_bfloat162 lp0(__float2bfloat16(v.x - __bfloat162float(h0)),
                               __float2bfloat16(v.y - __bfloat162float(h1)));
            __nv_bfloat162 lp1(__float2bfloat16(v.z - __bfloat162float(h2)),
                               __float2bfloat16(v.w - __bfloat162float(h3)));
            uint2 hw, lw;
            hw.x = *reinterpret_cast<uint32_t*>(&hp0);
            hw.y = *reinterpret_cast<uint32_t*>(&hp1);
            lw.x = *reinterpret_cast<uint32_t*>(&lp0);
            lw.y = *reinterpret_cast<uint32_t*>(&lp1);
            int off = row * LDH + kq;
            *reinterpret_cast<uint2*>(&sm[SM_AHI + off]) = hw;
            *reinterpret_cast<uint2*>(&sm[SM_ALO + off]) = lw;
        }
        // (b) W tile kt arrived
        cp_wait0();
        // (c) tile visible to all
        __syncthreads();

        // (d) prefetch next tile: X -> regs, W -> other smem stage
        if (kt < 3) {
            const int k0n = (kt + 1) * 64;
#pragma unroll
            for (int i = 0; i < 8; i++) {
                int slot = i * 256 + tid;
                int row  = slot >> 4;
                int kq   = (slot & 15) << 2;
                int gm   = block_row + row;
                xreg[i] = make_float4(0.f, 0.f, 0.f, 0.f);
                if (gm < NN)
                    xreg[i] = *reinterpret_cast<const float4*>(
                                  X + (size_t)gm * INC + k0n + kq);
            }
            const int nbuf = (kt + 1) & 1;
            const int nwhi = SM_W + nbuf * SM_WSTRIDE;
#pragma unroll
            for (int i = 0; i < 4; i++) {
                int slot = i * 256 + tid;
                int n    = slot >> 3;
                int kc   = (slot & 7) << 3;
                int off  = n * LDH + kc;
                cp_async16(sb + 2 * (nwhi + off),        g_Whi + n * INC + k0n + kc);
                cp_async16(sb + 2 * (nwhi + 9216 + off), g_Wlo + n * INC + k0n + kc);
            }
            cp_commit();
        }

        // (e) compute: 4 k16 steps
#pragma unroll
        for (int ks = 0; ks < 4; ks++) {
            uint32_t ah[2][4], al[2][4];
#pragma unroll
            for (int mi = 0; mi < 2; mi++) {
                int hoff = (wm + mi * 16 + a_row) * LDH + ks * 16 + a_kh;
                ldm_x4(ah[mi], sb + 2 * (SM_AHI + hoff));
                ldm_x4(al[mi], sb + 2 * (SM_ALO + hoff));
            }
#pragma unroll
            for (int ni = 0; ni < 8; ni++) {
                uint32_t bh[2], bl[2];
                int hoff = (wn + ni * 8 + b_row) * LDH + ks * 16 + b_kh;
                ldm_x2(bh, sb + 2 * (whi + hoff));
                ldm_x2(bl, sb + 2 * (wlo + hoff));
#pragma unroll
                for (int mi = 0; mi < 2; mi++) {
                    mma_bf16(c[mi][ni], ah[mi], bh);
                    mma_bf16(c[mi][ni], al[mi], bh);
                    mma_bf16(c[mi][ni], ah[mi], bl);
                }
            }
        }
        // (f) protect A smem before next overwrite
        __syncthreads();
    }

    // --- epilogue: write fp16 H ---
    const int r0 = (lane >> 2);
    const int cb = (lane & 3) * 2;
#pragma unroll
    for (int mi = 0; mi < 2; mi++) {
#pragma unroll
        for (int ni = 0; ni < 8; ni++) {
            int col = wn + ni * 8 + cb;
            int gm0 = block_row + wm + mi * 16 + r0;
            int gm1 = gm0 + 8;
            if (gm0 < NN)
                *reinterpret_cast<__half2*>(g_Hh + (size_t)gm0 * OUTC + col) =
                    __floats2half2_rn(c[mi][ni][0], c[mi][ni][1]);
            if (gm1 < NN)
                *reinterpret_cast<__half2*>(g_Hh + (size_t)gm1 * OUTC + col) =
                    __floats2half2_rn(c[mi][ni][2], c[mi][ni][3]);
        }
    }
}

// ------------------------- Kernel 2: CSR row pointers (A_rows sorted) -------------------------
__global__ void row_ptr_kernel(const int* __restrict__ A_rows)
{
    int r = blockIdx.x * blockDim.x + threadIdx.x;
    if (r > NN) return;
    int lo = 0, hi = EE;
    while (lo < hi) {
        int mid = (lo + hi) >> 1;
        if (A_rows[mid] < r) lo = mid + 1;
        else                 hi = mid;
    }
    g_row_ptr[r] = lo;
}

// ------------------------- Kernel 3: CSR SpMM, warp per row, paired edges -----------
// Half-warp per edge: lanes 0-15 -> edge j, lanes 16-31 -> edge j+1.
// Lane owns 8 channels (uint4 = 16B fp16). Per edge pair:
// 2 shfl + 1 LDG.128 + 4 cvt + 8 FMA. Final cross-half-warp shfl reduction.
__global__ __launch_bounds__(256)
void spmm_kernel(const int*   __restrict__ A_cols,
                 const float* __restrict__ A_vals,
                 float*       __restrict__ out)
{
    const int lane = threadIdx.x & 31;
    const int r    = blockIdx.x * 8 + (threadIdx.x >> 5);
    if (r >= NN) return;                       // warp-uniform

    const int hlf = lane >> 4;                 // which edge of the pair
    const int cl  = lane & 15;                 // channel group (8 ch)
    const int beg = g_row_ptr[r];
    const int end = g_row_ptr[r + 1];
    const __half* __restrict__ Hbase = g_Hh;

    float acc[8];
#pragma unroll
    for (int i = 0; i < 8; i++) acc[i] = 0.f;

#pragma unroll 1
    for (int base = beg; base < end; base += 32) {
        int   e   = base + lane;
        int   col = 0;
        float v   = 0.f;
        if (e < end) { col = __ldg(A_cols + e); v = __ldg(A_vals + e); }
        const int cnt = min(32, end - base);

#pragma unroll 4
        for (int j = 0; j < cnt; j += 2) {
            int   cj = __shfl_sync(0xffffffffu, col, j + hlf);
            float vj = __shfl_sync(0xffffffffu, v,   j + hlf);
            uint4 hraw = *reinterpret_cast<const uint4*>(
                             Hbase + (size_t)cj * OUTC + cl * 8);
            __half2 h0 = *reinterpret_cast<__half2*>(&hraw.x);
            __half2 h1 = *reinterpret_cast<__half2*>(&hraw.y);
            __half2 h2 = *reinterpret_cast<__half2*>(&hraw.z);
            __half2 h3 = *reinterpret_cast<__half2*>(&hraw.w);
            float2 f0 = __half22float2(h0);
            float2 f1 = __half22float2(h1);
            float2 f2 = __half22float2(h2);
            float2 f3 = __half22float2(h3);
            acc[0] = fmaf(vj, f0.x, acc[0]);
            acc[1] = fmaf(vj, f0.y, acc[1]);
            acc[2] = fmaf(vj, f1.x, acc[2]);
            acc[3] = fmaf(vj, f1.y, acc[3]);
            acc[4] = fmaf(vj, f2.x, acc[4]);
            acc[5] = fmaf(vj, f2.y, acc[5]);
            acc[6] = fmaf(vj, f3.x, acc[6]);
            acc[7] = fmaf(vj, f3.y, acc[7]);
        }
    }

    // combine the two half-warps (same channels, different edges)
#pragma unroll
    for (int i = 0; i < 8; i++)
        acc[i] += __shfl_xor_sync(0xffffffffu, acc[i], 16);

    if (hlf == 0) {
        float* dst = out + (size_t)r * OUTC + cl * 8;
        *reinterpret_cast<float4*>(dst + 0) =
            make_float4(acc[0], acc[1], acc[2], acc[3]);
        *reinterpret_cast<float4*>(dst + 4) =
            make_float4(acc[4], acc[5], acc[6], acc[7]);
    }
}

// ---------------------------------------------------------------------------
extern "C" void kernel_launch(void* const* d_in, const int* in_sizes, int n_in,
                              void* d_out, int out_size)
{
    const float* X      = (const float*)d_in[0];   // [NN, INC]
    const float* W      = (const float*)d_in[1];   // [OUTC, INC]
    const int*   A_rows = (const int*)  d_in[2];   // [EE] sorted
    const int*   A_cols = (const int*)  d_in[3];   // [EE]
    const float* A_vals = (const float*)d_in[4];   // [EE]
    float*       out    = (float*)d_out;           // [NN, OUTC]

    cudaFuncSetAttribute(gemm_tc_kernel,
                         cudaFuncAttributeMaxDynamicSharedMemorySize, SM_BYTES);

    wconv_kernel<<<(OUTC * INC + 255) / 256, 256>>>(W);
    gemm_tc_kernel<<<(NN + 127) / 128, 256, SM_BYTES>>>(X);
    row_ptr_kernel<<<(NN + 1 + 255) / 256, 256>>>(A_rows);
    spmm_kernel<<<(NN + 7) / 8, 256>>>(A_cols, A_vals, out);
}

// round 11
// speedup vs baseline: 1.3716x; 1.3716x over previous
#include <cuda_runtime.h>
#include <cuda_bf16.h>
#include <cuda_fp16.h>
#include <cstdint>

#define NN    100000
#define EE    1600000
#define INC   256
#define OUTC  128

// ------------------------- device scratch -------------------------
__device__ __half g_Hh[(size_t)NN * OUTC];    // H = X @ W^T (fp16)
__device__ int    g_row_ptr[NN + 1];
__device__ __half g_Wh[OUTC * INC];           // W in fp16

// ------------------------- helpers -------------------------
__device__ __forceinline__ uint32_t smem_u32(const void* p) {
    uint32_t a;
    asm("{ .reg .u64 t; cvta.to.shared.u64 t, %1; cvt.u32.u64 %0, t; }"
        : "=r"(a) : "l"(p));
    return a;
}
__device__ __forceinline__ void ldm_x4(uint32_t* r, uint32_t addr) {
    asm volatile("ldmatrix.sync.aligned.m8n8.x4.shared.b16 {%0,%1,%2,%3}, [%4];"
                 : "=r"(r[0]), "=r"(r[1]), "=r"(r[2]), "=r"(r[3]) : "r"(addr));
}
__device__ __forceinline__ void mma_fp16(float* c, const uint32_t* a, const uint32_t* b) {
    asm volatile(
        "mma.sync.aligned.m16n8k16.row.col.f32.f16.f16.f32 "
        "{%0,%1,%2,%3}, {%4,%5,%6,%7}, {%8,%9}, {%0,%1,%2,%3};"
        : "+f"(c[0]), "+f"(c[1]), "+f"(c[2]), "+f"(c[3])
        : "r"(a[0]), "r"(a[1]), "r"(a[2]), "r"(a[3]), "r"(b[0]), "r"(b[1]));
}

// ------------------------- Kernel 0: W -> fp16 -------------------------
__global__ void wconv_kernel(const float* __restrict__ W) {
    int i = blockIdx.x * blockDim.x + threadIdx.x;
    if (i < OUTC * INC)
        g_Wh[i] = __float2half_rn(W[i]);
}

// ------------------------- Kernel 1: fp16 mma.sync GEMM -------------------------
// H[m][n] = sum_k X[m][k] * W[n][k].  CTA tile 128x128, K-tiles of 64.
// 8 warps: warp_m = wid%4 (32 rows), warp_n = wid/4 (64 cols).
// SMEM (halves, row stride LDH=72 for conflict-free ldmatrix):
//   A[128][72], B[128][72]
#define LDH 72
#define SM_A 0
#define SM_B (128 * LDH)
#define SM_HALVES (2 * 128 * LDH)
#define SM_BYTES (SM_HALVES * 2)   // 36864

__global__ __launch_bounds__(256, 2)
void gemm_tc_kernel(const float* __restrict__ X)
{
    extern __shared__ __half sm[];
    const uint32_t sb = smem_u32(sm);

    const int tid = threadIdx.x;
    const int wid = tid >> 5;
    const int lane = tid & 31;
    const int block_row = blockIdx.x * 128;

    const int wm = (wid & 3) * 32;   // warp row offset
    const int wn = (wid >> 2) * 64;  // warp col offset

    float c[2][8][4];
#pragma unroll
    for (int mi = 0; mi < 2; mi++)
#pragma unroll
        for (int ni = 0; ni < 8; ni++)
#pragma unroll
            for (int j = 0; j < 4; j++)
                c[mi][ni][j] = 0.0f;

    // A ldmatrix.x4 lane mapping: 16 rows x 2 k-halves
    const int a_row = (lane & 7) + 8 * ((lane >> 3) & 1);
    const int a_kh  = 8 * (lane >> 4);
    // B ldmatrix.x4 lane mapping for an ni-PAIR (16 n-rows x 2 k-halves):
    //   lanes 0-7:   n-rows 0-7,  k0-7     lanes 8-15:  n-rows 0-7,  k8-15
    //   lanes 16-23: n-rows 8-15, k0-7     lanes 24-31: n-rows 8-15, k8-15
    const int b_row = (lane & 7) + 8 * (lane >> 4);
    const int b_kh  = 8 * ((lane >> 3) & 1);

#pragma unroll 1
    for (int kt = 0; kt < 4; kt++) {
        const int k0 = kt * 64;
        if (kt) __syncthreads();

        // --- X tile: 128 rows x 64 floats -> fp16 ---
#pragma unroll
        for (int i = 0; i < 8; i++) {
            int slot = i * 256 + tid;          // 0..2047 float4 slots
            int row  = slot >> 4;
            int kq   = (slot & 15) << 2;
            int gm   = block_row + row;
            float4 v = make_float4(0.f, 0.f, 0.f, 0.f);
            if (gm < NN)
                v = *reinterpret_cast<const float4*>(X + (size_t)gm * INC + k0 + kq);
            __half2 p0 = __floats2half2_rn(v.x, v.y);
            __half2 p1 = __floats2half2_rn(v.z, v.w);
            uint2 w;
            w.x = *reinterpret_cast<uint32_t*>(&p0);
            w.y = *reinterpret_cast<uint32_t*>(&p1);
            *reinterpret_cast<uint2*>(&sm[SM_A + row * LDH + kq]) = w;
        }
        // --- W tile: 128 n x 64 halves (preconverted fp16) ---
        // 1024 uint4 slots: 8 slots per n-row, 8 halves (16B) per slot.
#pragma unroll
        for (int i = 0; i < 4; i++) {
            int slot = i * 256 + tid;          // 0..1023
            int n    = slot >> 3;
            int kc   = (slot & 7) << 3;
            *reinterpret_cast<uint4*>(&sm[SM_B + n * LDH + kc]) =
                *reinterpret_cast<const uint4*>(g_Wh + n * INC + k0 + kc);
        }
        __syncthreads();

        // --- compute: 4 k16 steps ---
#pragma unroll
        for (int ks = 0; ks < 4; ks++) {
            uint32_t a[2][4];
#pragma unroll
            for (int mi = 0; mi < 2; mi++) {
                int hoff = (wm + mi * 16 + a_row) * LDH + ks * 16 + a_kh;
                ldm_x4(a[mi], sb + 2 * (SM_A + hoff));
            }
#pragma unroll
            for (int p = 0; p < 4; p++) {      // ni pairs (2p, 2p+1)
                uint32_t bq[4];
                int hoff = (wn + p * 16 + b_row) * LDH + ks * 16 + b_kh;
                ldm_x4(bq, sb + 2 * (SM_B + hoff));
#pragma unroll
                for (int mi = 0; mi < 2; mi++) {
                    mma_fp16(c[mi][2 * p + 0], a[mi], bq + 0);
                    mma_fp16(c[mi][2 * p + 1], a[mi], bq + 2);
                }
            }
        }
    }

    // --- epilogue: write fp16 H ---
    const int r0 = (lane >> 2);
    const int cb = (lane & 3) * 2;
#pragma unroll
    for (int mi = 0; mi < 2; mi++) {
#pragma unroll
        for (int ni = 0; ni < 8; ni++) {
            int col = wn + ni * 8 + cb;
            int gm0 = block_row + wm + mi * 16 + r0;
            int gm1 = gm0 + 8;
            if (gm0 < NN)
                *reinterpret_cast<__half2*>(g_Hh + (size_t)gm0 * OUTC + col) =
                    __floats2half2_rn(c[mi][ni][0], c[mi][ni][1]);
            if (gm1 < NN)
                *reinterpret_cast<__half2*>(g_Hh + (size_t)gm1 * OUTC + col) =
                    __floats2half2_rn(c[mi][ni][2], c[mi][ni][3]);
        }
    }
}

// ------------------------- Kernel 2: CSR row pointers (A_rows sorted) -------------------------
__global__ void row_ptr_kernel(const int* __restrict__ A_rows)
{
    int r = blockIdx.x * blockDim.x + threadIdx.x;
    if (r > NN) return;
    int lo = 0, hi = EE;
    while (lo < hi) {
        int mid = (lo + hi) >> 1;
        if (A_rows[mid] < r) lo = mid + 1;
        else                 hi = mid;
    }
    g_row_ptr[r] = lo;
}

// ------------------------- Kernel 3: CSR SpMM, warp per row (R8 proven) -------------
// Lane owns 4 channels (uint2 = 8B of fp16 H). Metadata via shuffles.
__global__ __launch_bounds__(256)
void spmm_kernel(const int*   __restrict__ A_cols,
                 const float* __restrict__ A_vals,
                 float*       __restrict__ out)
{
    const int lane = threadIdx.x & 31;
    const int r    = blockIdx.x * 8 + (threadIdx.x >> 5);
    if (r >= NN) return;                       // warp-uniform

    const int beg = g_row_ptr[r];
    const int end = g_row_ptr[r + 1];

    float4 acc = make_float4(0.f, 0.f, 0.f, 0.f);
    const __half* __restrict__ Hbase = g_Hh;

#pragma unroll 1
    for (int base = beg; base < end; base += 32) {
        int   e   = base + lane;
        int   col = 0;
        float v   = 0.f;
        if (e < end) { col = __ldg(A_cols + e); v = __ldg(A_vals + e); }
        const int cnt = min(32, end - base);

#pragma unroll 4
        for (int j = 0; j < cnt; j++) {
            int   cj = __shfl_sync(0xffffffffu, col, j);
            float vj = __shfl_sync(0xffffffffu, v,   j);
            uint2 hraw = *reinterpret_cast<const uint2*>(
                             Hbase + (size_t)cj * OUTC + lane * 4);
            __half2 h0 = *reinterpret_cast<__half2*>(&hraw.x);
            __half2 h1 = *reinterpret_cast<__half2*>(&hraw.y);
            float2 f0 = __half22float2(h0);
            float2 f1 = __half22float2(h1);
            acc.x = fmaf(vj, f0.x, acc.x);
            acc.y = fmaf(vj, f0.y, acc.y);
            acc.z = fmaf(vj, f1.x, acc.z);
            acc.w = fmaf(vj, f1.y, acc.w);
        }
    }

    *reinterpret_cast<float4*>(out + (size_t)r * OUTC + lane * 4) = acc;
}

// ---------------------------------------------------------------------------
extern "C" void kernel_launch(void* const* d_in, const int* in_sizes, int n_in,
                              void* d_out, int out_size)
{
    const float* X      = (const float*)d_in[0];   // [NN, INC]
    const float* W      = (const float*)d_in[1];   // [OUTC, INC]
    const int*   A_rows = (const int*)  d_in[2];   // [EE] sorted
    const int*   A_cols = (const int*)  d_in[3];   // [EE]
    const float* A_vals = (const float*)d_in[4];   // [EE]
    float*       out    = (float*)d_out;           // [NN, OUTC]

    cudaFuncSetAttribute(gemm_tc_kernel,
                         cudaFuncAttributeMaxDynamicSharedMemorySize, SM_BYTES);

    wconv_kernel<<<(OUTC * INC + 255) / 256, 256>>>(W);
    gemm_tc_kernel<<<(NN + 127) / 128, 256, SM_BYTES>>>(X);
    row_ptr_kernel<<<(NN + 1 + 255) / 256, 256>>>(A_rows);
    spmm_kernel<<<(NN + 7) / 8, 256>>>(A_cols, A_vals, out);
}